// round 1
// baseline (speedup 1.0000x reference)
#include <cuda_runtime.h>
#include <math.h>

#define B_ 2
#define T_ 2048
#define D_ 512
#define K_ 64
#define TT 32        // t-tile per block
#define WW 95        // window width actually used (TT + K - 1)
#define WP 97        // padded sq row stride (floats) -> conflict-free LDS
#define MP 96        // E row stride

// 8MB scratch for q = gelu(conv1d(x)) in [b][d][t] layout
__device__ float g_q[B_ * D_ * T_];

// ---------------------------------------------------------------------------
// Kernel A: q[b,d,t] = gelu(w0*x[t-1] + w1*x[t] + w2*x[t+1] + bias[d]) (exact erf gelu)
// ---------------------------------------------------------------------------
__global__ void conv_gelu_kernel(const float* __restrict__ x,
                                 const float* __restrict__ w,
                                 const float* __restrict__ bias) {
    int t = blockIdx.x * blockDim.x + threadIdx.x;
    int d = blockIdx.y;
    int b = blockIdx.z;
    float w0 = w[d * 3 + 0], w1 = w[d * 3 + 1], w2 = w[d * 3 + 2];
    float bb = bias[d];
    const float* xb = x + b * T_;
    float xm = (t > 0)      ? xb[t - 1] : 0.f;
    float xc = xb[t];
    float xp = (t < T_ - 1) ? xb[t + 1] : 0.f;
    float v = fmaf(w0, xm, fmaf(w1, xc, w2 * xp)) + bb;
    float g = 0.5f * v * (1.f + erff(v * 0.7071067811865476f));
    g_q[(b * D_ + d) * T_ + t] = g;
}

// ---------------------------------------------------------------------------
// Kernel B: fused banded energy (Gram band) + softmax + context, q window in smem.
// One block handles (b, t0..t0+31). Window smem: sq[512][97] (~199KB).
//   E[t][m] = sum_d sq[d][63+t] * sq[d][m],  m = t + k, band m in [t, t+63]
//   attn via softmax over k; context[t][d] = sum_w attn2[t][w] * sq[d][w]
// ---------------------------------------------------------------------------
extern __shared__ float smem[];

__global__ void __launch_bounds__(256, 1)
attn_kernel(const float* __restrict__ gate, float* __restrict__ out) {
    float* sq  = smem;                    // [512][97]
    float* E0  = smem + D_ * WP;          // [32][96]  energy half 0 -> attn2
    float* SCR = E0 + TT * MP;            // [128][33] energy half 1 / output stage

    const int tid = threadIdx.x;
    const int b   = blockIdx.y;
    const int t0  = blockIdx.x * TT;
    const float tgate = tanhf(gate[0]);

    // ---- load q window into smem (zero-fill left pad + stride pad cols) ----
    const float* qb = g_q + b * D_ * T_;
    for (int i = tid; i < D_ * WP; i += 256) {
        int d = i / WP, w = i - d * WP;
        int wt = t0 - (K_ - 1) + w;
        float v = 0.f;
        if (w < WW && wt >= 0) v = qb[d * T_ + wt];
        sq[i] = v;
    }
    __syncthreads();

    // ---- energy: full 32 x 96 rect (band superset), D split across halves ----
    {
        const int dz = tid >> 7;      // which half of D
        const int r  = tid & 127;
        const int tx = r & 15;        // m-group: m = tx + 16*j, j=0..5
        const int ty = r >> 4;        // t-group: t = ty + 8*i, i=0..3
        float acc[4][6];
        #pragma unroll
        for (int i = 0; i < 4; i++)
            #pragma unroll
            for (int j = 0; j < 6; j++) acc[i][j] = 0.f;

        const float* sqd = sq + dz * 256 * WP;
        #pragma unroll 2
        for (int d = 0; d < 256; ++d) {
            const float* row = sqd + d * WP;
            float a[4], bv[6];
            #pragma unroll
            for (int i = 0; i < 4; i++) a[i] = row[63 + ty + 8 * i];
            #pragma unroll
            for (int j = 0; j < 6; j++) bv[j] = row[tx + 16 * j];
            #pragma unroll
            for (int i = 0; i < 4; i++)
                #pragma unroll
                for (int j = 0; j < 6; j++) acc[i][j] = fmaf(a[i], bv[j], acc[i][j]);
        }
        float* Eo = dz ? SCR : E0;
        #pragma unroll
        for (int i = 0; i < 4; i++)
            #pragma unroll
            for (int j = 0; j < 6; j++)
                Eo[(ty + 8 * i) * MP + tx + 16 * j] = acc[i][j];
    }
    __syncthreads();

    // ---- softmax over k (band m in [t, t+63]); write attn2 into E0 (0 outside) ----
    {
        const int warp = tid >> 5, lane = tid & 31;
        const float S = 0.04419417382415922f;  // 1/sqrt(512)
        for (int t = warp; t < TT; t += 8) {
            float e1 = E0[t * MP + t + lane]      + SCR[t * MP + t + lane];
            float e2 = E0[t * MP + t + lane + 32] + SCR[t * MP + t + lane + 32];
            float mx = fmaxf(e1, e2);
            #pragma unroll
            for (int o = 16; o; o >>= 1) mx = fmaxf(mx, __shfl_xor_sync(0xffffffffu, mx, o));
            float p1 = expf((e1 - mx) * S);
            float p2 = expf((e2 - mx) * S);
            float sm = p1 + p2;
            #pragma unroll
            for (int o = 16; o; o >>= 1) sm += __shfl_xor_sync(0xffffffffu, sm, o);
            float inv = 1.f / sm;
            // zero whole row (3 cols/lane), then write band values (program order safe)
            E0[t * MP + lane]      = 0.f;
            E0[t * MP + lane + 32] = 0.f;
            E0[t * MP + lane + 64] = 0.f;
            E0[t * MP + t + lane]      = p1 * inv;
            E0[t * MP + t + lane + 32] = p2 * inv;
        }
    }
    __syncthreads();

    // ---- context GEMM: C[t][d] = sum_w E0[t][w] * sq[d][w], 4 chunks of 128 d ----
    {
        const int tx = tid & 31;   // d lane: d = d0 + tx + 32*j, j=0..3
        const int ty = tid >> 5;   // t group: t = ty + 8*i, i=0..3
        for (int c = 0; c < 4; ++c) {
            const int d0 = c * 128;
            float acc[4][4];
            #pragma unroll
            for (int i = 0; i < 4; i++)
                #pragma unroll
                for (int j = 0; j < 4; j++) acc[i][j] = 0.f;

            #pragma unroll 1
            for (int w = 0; w < WW; ++w) {
                float av[4], bv[4];
                #pragma unroll
                for (int i = 0; i < 4; i++) av[i] = E0[(ty + 8 * i) * MP + w];
                #pragma unroll
                for (int j = 0; j < 4; j++) bv[j] = sq[(d0 + tx + 32 * j) * WP + w];
                #pragma unroll
                for (int i = 0; i < 4; i++)
                    #pragma unroll
                    for (int j = 0; j < 4; j++) acc[i][j] = fmaf(av[i], bv[j], acc[i][j]);
            }
            // stage through smem for coalesced global writes
            #pragma unroll
            for (int i = 0; i < 4; i++)
                #pragma unroll
                for (int j = 0; j < 4; j++)
                    SCR[(tx + 32 * j) * 33 + ty + 8 * i] = acc[i][j];
            __syncthreads();
            float* ob = out + (size_t)(b * D_ + d0) * T_ + t0;
            #pragma unroll
            for (int r2 = 0; r2 < 16; ++r2) {
                int idx = r2 * 256 + tid;
                int dl = idx >> 5, t = idx & 31;
                ob[dl * T_ + t] = SCR[dl * 33 + t] * tgate;
            }
            __syncthreads();
        }
    }
}

// ---------------------------------------------------------------------------
extern "C" void kernel_launch(void* const* d_in, const int* in_sizes, int n_in,
                              void* d_out, int out_size) {
    const float* x      = (const float*)d_in[0];  // (2,1,2048)
    const float* conv_w = (const float*)d_in[1];  // (512,1,3)
    const float* conv_b = (const float*)d_in[2];  // (512,)
    const float* gate   = (const float*)d_in[3];  // scalar
    float* out = (float*)d_out;                   // (2,512,2048)

    (void)in_sizes; (void)n_in; (void)out_size;

    dim3 gA(T_ / 256, D_, B_);
    conv_gelu_kernel<<<gA, 256>>>(x, conv_w, conv_b);

    const int smem_bytes = (D_ * WP + TT * MP + 128 * 33) * (int)sizeof(float); // 227,840
    cudaFuncSetAttribute(attn_kernel, cudaFuncAttributeMaxDynamicSharedMemorySize, smem_bytes);
    dim3 gB(T_ / TT, B_);
    attn_kernel<<<gB, 256, smem_bytes>>>(gate, out);
}

// round 2
// speedup vs baseline: 1.1834x; 1.1834x over previous
#include <cuda_runtime.h>
#include <math.h>

#define B_ 2
#define T_ 2048
#define D_ 512
#define K_ 64
#define TT 32        // t-tile per block
#define WW 95        // window width actually used (TT + K - 1)
#define WP 100       // padded sq row stride: 16B-aligned rows, conflict-free LDS.128
#define MP 96        // E row stride (16B-aligned)

// 8MB scratch for q = gelu(conv1d(x)) in [b][d][t] layout
__device__ float g_q[B_ * D_ * T_];

// ---------------------------------------------------------------------------
// Kernel A: q[b,d,t] = gelu(w0*x[t-1] + w1*x[t] + w2*x[t+1] + bias[d]) (exact)
// ---------------------------------------------------------------------------
__global__ void conv_gelu_kernel(const float* __restrict__ x,
                                 const float* __restrict__ w,
                                 const float* __restrict__ bias) {
    int t = blockIdx.x * blockDim.x + threadIdx.x;
    int d = blockIdx.y;
    int b = blockIdx.z;
    float w0 = w[d * 3 + 0], w1 = w[d * 3 + 1], w2 = w[d * 3 + 2];
    float bb = bias[d];
    const float* xb = x + b * T_;
    float xm = (t > 0)      ? xb[t - 1] : 0.f;
    float xc = xb[t];
    float xp = (t < T_ - 1) ? xb[t + 1] : 0.f;
    float v = fmaf(w0, xm, fmaf(w1, xc, w2 * xp)) + bb;
    float g = 0.5f * v * (1.f + erff(v * 0.7071067811865476f));
    g_q[(b * D_ + d) * T_ + t] = g;
}

// ---------------------------------------------------------------------------
// Kernel B: fused banded energy + softmax + context; q window in smem.
// One block per (b, 32-t tile). smem: sq[512][100] + E0[32][96] + E1[32][96]
// ---------------------------------------------------------------------------
extern __shared__ float smem[];

__global__ void __launch_bounds__(256, 1)
attn_kernel(const float* __restrict__ gate, float* __restrict__ out) {
    float* sq = smem;                     // [512][100]
    float* E0 = smem + D_ * WP;           // [32][96]  energy half 0 -> attn
    float* E1 = E0 + TT * MP;             // [32][96]  energy half 1

    const int tid = threadIdx.x;
    const int b   = blockIdx.y;
    const int t0  = blockIdx.x * TT;
    const float tgate = tanhf(gate[0]);

    // ---- load q window into smem (zero-fill left pad + stride pad cols) ----
    const float* qb = g_q + b * D_ * T_;
    for (int i = tid; i < D_ * WP; i += 256) {
        int d = i / WP, w = i - d * WP;
        int wt = t0 - (K_ - 1) + w;
        float v = 0.f;
        if (w < WW && wt >= 0) v = qb[d * T_ + wt];
        sq[i] = v;
    }
    __syncthreads();

    // ---- energy: 32 x 96 rect (band superset), D split across thread halves ----
    {
        const int dz = tid >> 7;      // which half of D (0/1)
        const int r  = tid & 127;
        const int tx = r & 15;        // m pair-group: m = 2*tx + 32*j (+0/1)
        const int ty = r >> 4;        // t-group: t = ty + 8*i
        float acc[4][6];
        #pragma unroll
        for (int i = 0; i < 4; i++)
            #pragma unroll
            for (int j = 0; j < 6; j++) acc[i][j] = 0.f;

        const float* sqd = sq + dz * 256 * WP;
        #pragma unroll 2
        for (int d = 0; d < 256; ++d) {
            const float* row = sqd + d * WP;
            float a[4];
            #pragma unroll
            for (int i = 0; i < 4; i++) a[i] = row[63 + ty + 8 * i];
            float2 bv[3];
            #pragma unroll
            for (int j = 0; j < 3; j++)
                bv[j] = *(const float2*)(row + 2 * tx + 32 * j);
            #pragma unroll
            for (int i = 0; i < 4; i++)
                #pragma unroll
                for (int j = 0; j < 3; j++) {
                    acc[i][2*j]   = fmaf(a[i], bv[j].x, acc[i][2*j]);
                    acc[i][2*j+1] = fmaf(a[i], bv[j].y, acc[i][2*j+1]);
                }
        }
        float* Eo = dz ? E1 : E0;
        #pragma unroll
        for (int i = 0; i < 4; i++)
            #pragma unroll
            for (int j = 0; j < 3; j++)
                *(float2*)(Eo + (ty + 8 * i) * MP + 2 * tx + 32 * j) =
                    make_float2(acc[i][2*j], acc[i][2*j+1]);
    }
    __syncthreads();

    // ---- softmax over k (band m in [t, t+63]); attn into E0, zero elsewhere ----
    {
        const int warp = tid >> 5, lane = tid & 31;
        const float S = 0.04419417382415922f;  // 1/sqrt(512)
        for (int t = warp; t < TT; t += 8) {
            float e1 = E0[t * MP + t + lane]      + E1[t * MP + t + lane];
            float e2 = E0[t * MP + t + lane + 32] + E1[t * MP + t + lane + 32];
            float mx = fmaxf(e1, e2);
            #pragma unroll
            for (int o = 16; o; o >>= 1) mx = fmaxf(mx, __shfl_xor_sync(0xffffffffu, mx, o));
            float p1 = expf((e1 - mx) * S);
            float p2 = expf((e2 - mx) * S);
            float sm = p1 + p2;
            #pragma unroll
            for (int o = 16; o; o >>= 1) sm += __shfl_xor_sync(0xffffffffu, sm, o);
            float inv = 1.f / sm;
            // zero whole row (3 cols/lane), then write band values (program order safe)
            E0[t * MP + lane]      = 0.f;
            E0[t * MP + lane + 32] = 0.f;
            E0[t * MP + lane + 64] = 0.f;
            E0[t * MP + t + lane]      = p1 * inv;
            E0[t * MP + t + lane + 32] = p2 * inv;
        }
    }
    __syncthreads();

    // ---- context: C[t][d] = sum_w E0[t][w] * sq[d][w], float4 over w ----
    {
        const int tx = tid & 31;   // d lane: d = d0 + tx + 32*j, j=0..3
        const int ty = tid >> 5;   // t group: t = 4*ty + i, i=0..3 (consecutive)
        #pragma unroll 1
        for (int c = 0; c < 4; ++c) {
            const int d0 = c * 128;
            float acc[4][4];
            #pragma unroll
            for (int i = 0; i < 4; i++)
                #pragma unroll
                for (int j = 0; j < 4; j++) acc[i][j] = 0.f;

            const float* bbase = sq + (d0 + tx) * WP;
            #pragma unroll 2
            for (int w = 0; w < 96; w += 4) {
                float4 av[4], bv[4];
                #pragma unroll
                for (int i = 0; i < 4; i++)
                    av[i] = *(const float4*)(E0 + (4 * ty + i) * MP + w);
                #pragma unroll
                for (int j = 0; j < 4; j++)
                    bv[j] = *(const float4*)(bbase + j * 32 * WP + w);
                #pragma unroll
                for (int i = 0; i < 4; i++)
                    #pragma unroll
                    for (int j = 0; j < 4; j++) {
                        acc[i][j] = fmaf(av[i].x, bv[j].x, acc[i][j]);
                        acc[i][j] = fmaf(av[i].y, bv[j].y, acc[i][j]);
                        acc[i][j] = fmaf(av[i].z, bv[j].z, acc[i][j]);
                        acc[i][j] = fmaf(av[i].w, bv[j].w, acc[i][j]);
                    }
            }
            // direct coalesced-enough STG.128: 4 consecutive t per thread
            #pragma unroll
            for (int j = 0; j < 4; j++) {
                float* op = out + (size_t)(b * D_ + d0 + tx + 32 * j) * T_ + t0 + 4 * ty;
                *(float4*)op = make_float4(acc[0][j] * tgate, acc[1][j] * tgate,
                                           acc[2][j] * tgate, acc[3][j] * tgate);
            }
        }
    }
}

// ---------------------------------------------------------------------------
extern "C" void kernel_launch(void* const* d_in, const int* in_sizes, int n_in,
                              void* d_out, int out_size) {
    const float* x      = (const float*)d_in[0];  // (2,1,2048)
    const float* conv_w = (const float*)d_in[1];  // (512,1,3)
    const float* conv_b = (const float*)d_in[2];  // (512,)
    const float* gate   = (const float*)d_in[3];  // scalar
    float* out = (float*)d_out;                   // (2,512,2048)

    (void)in_sizes; (void)n_in; (void)out_size;

    dim3 gA(T_ / 256, D_, B_);
    conv_gelu_kernel<<<gA, 256>>>(x, conv_w, conv_b);

    const int smem_bytes = (D_ * WP + 2 * TT * MP) * (int)sizeof(float); // 229,376
    cudaFuncSetAttribute(attn_kernel, cudaFuncAttributeMaxDynamicSharedMemorySize, smem_bytes);
    dim3 gB(T_ / TT, B_);
    attn_kernel<<<gB, 256, smem_bytes>>>(gate, out);
}

// round 3
// speedup vs baseline: 1.5980x; 1.3503x over previous
#include <cuda_runtime.h>
#include <math.h>

#define B_ 2
#define T_ 2048
#define D_ 512
#define K_ 64
#define TT 32        // t-tile per block
#define WW 95        // window width actually used (TT + K - 1)
#define WP 100       // padded sq row stride (16B-aligned, LDS.128 conflict-free)
#define MP 96        // E row stride

// 8MB scratch for q = gelu(conv1d(x)) in [b][d][t] layout
__device__ float g_q[B_ * D_ * T_];

// ---------------------------------------------------------------------------
// Kernel A: q[b,d,t] = gelu(conv1d(x)) exact erf gelu
// ---------------------------------------------------------------------------
__global__ void conv_gelu_kernel(const float* __restrict__ x,
                                 const float* __restrict__ w,
                                 const float* __restrict__ bias) {
    int t = blockIdx.x * blockDim.x + threadIdx.x;
    int d = blockIdx.y;
    int b = blockIdx.z;
    float w0 = w[d * 3 + 0], w1 = w[d * 3 + 1], w2 = w[d * 3 + 2];
    float bb = bias[d];
    const float* xb = x + b * T_;
    float xm = (t > 0)      ? xb[t - 1] : 0.f;
    float xc = xb[t];
    float xp = (t < T_ - 1) ? xb[t + 1] : 0.f;
    float v = fmaf(w0, xm, fmaf(w1, xc, w2 * xp)) + bb;
    float g = 0.5f * v * (1.f + erff(v * 0.7071067811865476f));
    g_q[(b * D_ + d) * T_ + t] = g;
}

// ---------------------------------------------------------------------------
// Kernel B: fused banded energy + softmax + context. 512 threads/block.
// smem: sq[512][100] + E0[32][96] + E1[32][96] = 229,376 B
// ---------------------------------------------------------------------------
extern __shared__ float smem[];

__global__ void __launch_bounds__(512, 1)
attn_kernel(const float* __restrict__ gate, float* __restrict__ out) {
    float* sq = smem;                     // [512][100]
    float* E0 = smem + D_ * WP;           // [32][96]
    float* E1 = E0 + TT * MP;             // [32][96]

    const int tid = threadIdx.x;
    const int b   = blockIdx.y;
    const int t0  = blockIdx.x * TT;
    const float tgate = tanhf(gate[0]);

    // ---- load q window into smem (zero-fill pads) ----
    const float* qb = g_q + b * D_ * T_;
    for (int i = tid; i < D_ * WP; i += 512) {
        int d = i / WP, w = i - d * WP;
        int wt = t0 - (K_ - 1) + w;
        float v = 0.f;
        if (w < WW && wt >= 0) v = qb[d * T_ + wt];
        sq[i] = v;
    }
    __syncthreads();

    // ---- energy: 32 x 96 rect, D split in 4 quarters across thread groups ----
    {
        const int qz = tid >> 7;      // D quarter (0..3)
        const int r  = tid & 127;
        const int tx = r & 15;        // m pair-group
        const int ty = r >> 4;        // t-group
        float acc[4][6];
        #pragma unroll
        for (int i = 0; i < 4; i++)
            #pragma unroll
            for (int j = 0; j < 6; j++) acc[i][j] = 0.f;

        const float* sqd = sq + qz * 128 * WP;
        #pragma unroll 2
        for (int d = 0; d < 128; ++d) {
            const float* row = sqd + d * WP;
            float a[4];
            #pragma unroll
            for (int i = 0; i < 4; i++) a[i] = row[63 + ty + 8 * i];
            float2 bv[3];
            #pragma unroll
            for (int j = 0; j < 3; j++)
                bv[j] = *(const float2*)(row + 2 * tx + 32 * j);
            #pragma unroll
            for (int i = 0; i < 4; i++)
                #pragma unroll
                for (int j = 0; j < 3; j++) {
                    acc[i][2*j]   = fmaf(a[i], bv[j].x, acc[i][2*j]);
                    acc[i][2*j+1] = fmaf(a[i], bv[j].y, acc[i][2*j+1]);
                }
        }
        // phase 1: quarters 0,1 store to E0,E1
        float* Eo = (qz & 1) ? E1 : E0;
        if (qz < 2) {
            #pragma unroll
            for (int i = 0; i < 4; i++)
                #pragma unroll
                for (int j = 0; j < 3; j++)
                    *(float2*)(Eo + (ty + 8 * i) * MP + 2 * tx + 32 * j) =
                        make_float2(acc[i][2*j], acc[i][2*j+1]);
        }
        __syncthreads();
        // phase 2: quarters 2,3 accumulate
        if (qz >= 2) {
            #pragma unroll
            for (int i = 0; i < 4; i++)
                #pragma unroll
                for (int j = 0; j < 3; j++) {
                    float2* p = (float2*)(Eo + (ty + 8 * i) * MP + 2 * tx + 32 * j);
                    float2 v = *p;
                    v.x += acc[i][2*j];
                    v.y += acc[i][2*j+1];
                    *p = v;
                }
        }
    }
    __syncthreads();

    // ---- softmax over k (band m in [t, t+63]); attn into E0, zero elsewhere ----
    {
        const int warp = tid >> 5, lane = tid & 31;
        const float S = 0.04419417382415922f;  // 1/sqrt(512)
        for (int t = warp; t < TT; t += 16) {
            float e1 = E0[t * MP + t + lane]      + E1[t * MP + t + lane];
            float e2 = E0[t * MP + t + lane + 32] + E1[t * MP + t + lane + 32];
            float mx = fmaxf(e1, e2);
            #pragma unroll
            for (int o = 16; o; o >>= 1) mx = fmaxf(mx, __shfl_xor_sync(0xffffffffu, mx, o));
            float p1 = expf((e1 - mx) * S);
            float p2 = expf((e2 - mx) * S);
            float sm = p1 + p2;
            #pragma unroll
            for (int o = 16; o; o >>= 1) sm += __shfl_xor_sync(0xffffffffu, sm, o);
            float inv = 1.f / sm;
            E0[t * MP + lane]      = 0.f;
            E0[t * MP + lane + 32] = 0.f;
            E0[t * MP + lane + 64] = 0.f;
            E0[t * MP + t + lane]      = p1 * inv;
            E0[t * MP + t + lane + 32] = p2 * inv;
        }
    }
    __syncthreads();

    // ---- context: C[t][d] = sum_w attn[t][w] * sq[d][w]; 8t x 4d microtile ----
    {
        const int tx = tid & 127;  // d lane: d = tx + 128*j, j=0..3
        const int ty = tid >> 7;   // t group: t = 8*ty + i, i=0..7
        const int w0 = 8 * ty;     // band-trimmed w start (18 float4 steps)
        float acc[8][4];
        #pragma unroll
        for (int i = 0; i < 8; i++)
            #pragma unroll
            for (int j = 0; j < 4; j++) acc[i][j] = 0.f;

        const float* bbase = sq + tx * WP;
        const float* abase = E0 + 8 * ty * MP;
        #pragma unroll 2
        for (int s = 0; s < 18; ++s) {
            const int w = w0 + 4 * s;
            float4 av[8], bv[4];
            #pragma unroll
            for (int i = 0; i < 8; i++)
                av[i] = *(const float4*)(abase + i * MP + w);
            #pragma unroll
            for (int j = 0; j < 4; j++)
                bv[j] = *(const float4*)(bbase + j * 128 * WP + w);
            #pragma unroll
            for (int i = 0; i < 8; i++)
                #pragma unroll
                for (int j = 0; j < 4; j++) {
                    acc[i][j] = fmaf(av[i].x, bv[j].x, acc[i][j]);
                    acc[i][j] = fmaf(av[i].y, bv[j].y, acc[i][j]);
                    acc[i][j] = fmaf(av[i].z, bv[j].z, acc[i][j]);
                    acc[i][j] = fmaf(av[i].w, bv[j].w, acc[i][j]);
                }
        }
        // direct STG.128: 8 consecutive t per thread (two float4 per d)
        #pragma unroll
        for (int j = 0; j < 4; j++) {
            float* op = out + (size_t)(b * D_ + tx + 128 * j) * T_ + t0 + 8 * ty;
            *(float4*)op       = make_float4(acc[0][j] * tgate, acc[1][j] * tgate,
                                             acc[2][j] * tgate, acc[3][j] * tgate);
            *(float4*)(op + 4) = make_float4(acc[4][j] * tgate, acc[5][j] * tgate,
                                             acc[6][j] * tgate, acc[7][j] * tgate);
        }
    }
}

// ---------------------------------------------------------------------------
extern "C" void kernel_launch(void* const* d_in, const int* in_sizes, int n_in,
                              void* d_out, int out_size) {
    const float* x      = (const float*)d_in[0];  // (2,1,2048)
    const float* conv_w = (const float*)d_in[1];  // (512,1,3)
    const float* conv_b = (const float*)d_in[2];  // (512,)
    const float* gate   = (const float*)d_in[3];  // scalar
    float* out = (float*)d_out;                   // (2,512,2048)

    (void)in_sizes; (void)n_in; (void)out_size;

    dim3 gA(T_ / 256, D_, B_);
    conv_gelu_kernel<<<gA, 256>>>(x, conv_w, conv_b);

    const int smem_bytes = (D_ * WP + 2 * TT * MP) * (int)sizeof(float); // 229,376
    cudaFuncSetAttribute(attn_kernel, cudaFuncAttributeMaxDynamicSharedMemorySize, smem_bytes);
    dim3 gB(T_ / TT, B_);
    attn_kernel<<<gB, 512, smem_bytes>>>(gate, out);
}